// round 16
// baseline (speedup 1.0000x reference)
#include <cuda_runtime.h>
#include <cuda_bf16.h>
#include <cstdint>
#include <math.h>

#define RTOT  8192              // B*N rows
#define SEQ   4096              // per-batch sequence length
#define DIM   1024
#define BANDW 640               // padded band width per row-block
#define LN_EPS 1e-6f
#define RD (RTOT * DIM)
#define BANDE ((size_t)RTOT * BANDW)

// Scratch (float units):
//  parity p in {0,1}: K/Q/V split-plane pairs (3*RD floats per parity)
//  [6RD, 8RD)   bA0, bA1 (parity)
//  [8RD, 9RD)   ySum
//  [9RD, 10RD)  woOut
//  [10RD, ...)  band
__device__ float g_scratch[10 * RD + BANDE];

// ============================================================================
// mma.sync helpers
// ============================================================================
__device__ __forceinline__ unsigned int smem_to_u32(const void* p) {
    unsigned int a;
    asm("{ .reg .u64 t; cvta.to.shared.u64 t, %1; cvt.u32.u64 %0, t; }"
        : "=r"(a) : "l"(p));
    return a;
}

__device__ __forceinline__ void ldsm4(unsigned int& r0, unsigned int& r1,
                                      unsigned int& r2, unsigned int& r3,
                                      unsigned int addr) {
    asm volatile("ldmatrix.sync.aligned.m8n8.x4.shared.b16 {%0,%1,%2,%3}, [%4];"
                 : "=r"(r0), "=r"(r1), "=r"(r2), "=r"(r3) : "r"(addr));
}
__device__ __forceinline__ void ldsm4t(unsigned int& r0, unsigned int& r1,
                                       unsigned int& r2, unsigned int& r3,
                                       unsigned int addr) {
    asm volatile("ldmatrix.sync.aligned.m8n8.x4.trans.shared.b16 {%0,%1,%2,%3}, [%4];"
                 : "=r"(r0), "=r"(r1), "=r"(r2), "=r"(r3) : "r"(addr));
}

__device__ __forceinline__ void mma16816(float* c, unsigned int a0, unsigned int a1,
                                         unsigned int a2, unsigned int a3,
                                         unsigned int b0, unsigned int b1) {
    asm volatile(
        "mma.sync.aligned.m16n8k16.row.col.f32.bf16.bf16.f32 "
        "{%0,%1,%2,%3}, {%4,%5,%6,%7}, {%8,%9}, {%0,%1,%2,%3};"
        : "+f"(c[0]), "+f"(c[1]), "+f"(c[2]), "+f"(c[3])
        : "r"(a0), "r"(a1), "r"(a2), "r"(a3), "r"(b0), "r"(b1));
}

__device__ __forceinline__ unsigned short bfu(float f) {
    return __bfloat16_as_ushort(__float2bfloat16(f));
}
__device__ __forceinline__ float bff(unsigned short u) {
    return __bfloat162float(__ushort_as_bfloat16(u));
}

__device__ __forceinline__ void split4(float4 v, uint2& uh, uint2& ul) {
    unsigned short hx = bfu(v.x), hy = bfu(v.y), hz = bfu(v.z), hw = bfu(v.w);
    uh = make_uint2((unsigned int)hx | ((unsigned int)hy << 16),
                    (unsigned int)hz | ((unsigned int)hw << 16));
    unsigned short lx = bfu(v.x - bff(hx)), ly = bfu(v.y - bff(hy));
    unsigned short lz = bfu(v.z - bff(hz)), lw = bfu(v.w - bff(hw));
    ul = make_uint2((unsigned int)lx | ((unsigned int)ly << 16),
                    (unsigned int)lz | ((unsigned int)lw << 16));
}

// ============================================================================
// tgemm: acc = alpha*(A[M,1024] @ B[Nn,1024]^T).
//   Chi/Clo non-null -> split bf16 planes; else fp32 C (+bias)(+relu)
// CTA 128x128, BK=64, 8 warps (4M x 2N), bf16-split-3 accumulation.
// MMA issue is TERM-MAJOR: 16 independent accs between any acc reuse.
// ============================================================================
#define PADR 72
#define TILE_B (128 * PADR * 2)
#define OFF_AHI 0
#define OFF_ALO (1 * TILE_B)
#define OFF_BHI (2 * TILE_B)
#define OFF_BLO (3 * TILE_B)
#define SMT     (4 * TILE_B)

__global__ void __launch_bounds__(256, 2)
tgemm(const float* __restrict__ A, const float* __restrict__ B,
      const float* __restrict__ bias, float* __restrict__ C,
      __nv_bfloat16* __restrict__ Chi, __nv_bfloat16* __restrict__ Clo,
      int Nn, float alpha, int relu)
{
    extern __shared__ __align__(16) char smc[];
    const unsigned int sbase = smem_to_u32(smc);
    const int tid = threadIdx.x;
    const int lane = tid & 31;
    const int wid = tid >> 5;
    const int wm = wid & 3;
    const int wn = wid >> 2;
    const int m0 = blockIdx.y << 7;
    const int n0 = blockIdx.x << 7;

    float acc[2][8][4];
#pragma unroll
    for (int i = 0; i < 2; i++)
#pragma unroll
        for (int j = 0; j < 8; j++)
#pragma unroll
            for (int c = 0; c < 4; c++) acc[i][j][c] = 0.f;

    const int lrow = tid >> 2;
    const int lseg = (tid & 3) << 2;

    const unsigned int a_off =
        (unsigned int)((wm * 32 + (lane & 15)) * PADR + ((lane >> 4) << 3)) * 2;
    const unsigned int b_off =
        (unsigned int)((wn * 64 + (lane & 7) + ((lane >> 4) << 3)) * PADR +
                       (((lane >> 3) & 1) << 3)) * 2;

    for (int kc = 0; kc < DIM / 64; kc++) {
        const int k0 = kc * 64;
        __syncthreads();
#pragma unroll
        for (int half = 0; half < 2; half++) {
            const int r = lrow + half * 64;
            const float4* ap = (const float4*)(A + (size_t)(m0 + r) * DIM + k0);
            const float4* bp = (const float4*)(B + (size_t)(n0 + r) * DIM + k0);
#pragma unroll
            for (int j = 0; j < 4; j++) {
                const int q = lseg + j;
                uint2 uh, ul;
                split4(ap[q], uh, ul);
                const int so = (r * PADR + q * 4) * 2;
                *(uint2*)(smc + OFF_AHI + so) = uh;
                *(uint2*)(smc + OFF_ALO + so) = ul;
                split4(bp[q], uh, ul);
                *(uint2*)(smc + OFF_BHI + so) = uh;
                *(uint2*)(smc + OFF_BLO + so) = ul;
            }
        }
        __syncthreads();
#pragma unroll
        for (int ks = 0; ks < 4; ks++) {
            const unsigned int kb = (unsigned int)(ks * 16) * 2;
            unsigned int ahi[2][4], alo[2][4];
#pragma unroll
            for (int mt = 0; mt < 2; mt++) {
                const unsigned int ad = sbase + (unsigned int)(mt * 16 * PADR * 2) + a_off + kb;
                ldsm4(ahi[mt][0], ahi[mt][1], ahi[mt][2], ahi[mt][3], ad + OFF_AHI);
                ldsm4(alo[mt][0], alo[mt][1], alo[mt][2], alo[mt][3], ad + OFF_ALO);
            }
            unsigned int bhi[8][2], blo[8][2];
#pragma unroll
            for (int np = 0; np < 4; np++) {
                const unsigned int bd = sbase + (unsigned int)(np * 16 * PADR * 2) + b_off + kb;
                unsigned int r0, r1, r2, r3;
                ldsm4(r0, r1, r2, r3, bd + OFF_BHI);
                bhi[2*np][0] = r0; bhi[2*np][1] = r1;
                bhi[2*np+1][0] = r2; bhi[2*np+1][1] = r3;
                ldsm4(r0, r1, r2, r3, bd + OFF_BLO);
                blo[2*np][0] = r0; blo[2*np][1] = r1;
                blo[2*np+1][0] = r2; blo[2*np+1][1] = r3;
            }
            // term-major issue: all 16 accs per term -> no back-to-back RAW
#pragma unroll
            for (int mt = 0; mt < 2; mt++)
#pragma unroll
                for (int nt = 0; nt < 8; nt++)
                    mma16816(acc[mt][nt], ahi[mt][0], ahi[mt][1], ahi[mt][2], ahi[mt][3],
                             bhi[nt][0], bhi[nt][1]);
#pragma unroll
            for (int mt = 0; mt < 2; mt++)
#pragma unroll
                for (int nt = 0; nt < 8; nt++)
                    mma16816(acc[mt][nt], ahi[mt][0], ahi[mt][1], ahi[mt][2], ahi[mt][3],
                             blo[nt][0], blo[nt][1]);
#pragma unroll
            for (int mt = 0; mt < 2; mt++)
#pragma unroll
                for (int nt = 0; nt < 8; nt++)
                    mma16816(acc[mt][nt], alo[mt][0], alo[mt][1], alo[mt][2], alo[mt][3],
                             bhi[nt][0], bhi[nt][1]);
        }
    }

    const int group = lane >> 2, tig = lane & 3;
    if (Chi) {
#pragma unroll
        for (int mt = 0; mt < 2; mt++)
#pragma unroll
            for (int nt = 0; nt < 8; nt++) {
                const int col = n0 + wn * 64 + nt * 8 + tig * 2;
#pragma unroll
                for (int h = 0; h < 2; h++) {
                    const int row = m0 + wm * 32 + mt * 16 + group + h * 8;
                    float v0 = alpha * acc[mt][nt][2 * h];
                    float v1 = alpha * acc[mt][nt][2 * h + 1];
                    unsigned short h0 = bfu(v0), h1 = bfu(v1);
                    unsigned short l0 = bfu(v0 - bff(h0)), l1 = bfu(v1 - bff(h1));
                    const size_t o = (size_t)row * Nn + col;
                    *(unsigned int*)(Chi + o) = (unsigned int)h0 | ((unsigned int)h1 << 16);
                    *(unsigned int*)(Clo + o) = (unsigned int)l0 | ((unsigned int)l1 << 16);
                }
            }
    } else {
#pragma unroll
        for (int mt = 0; mt < 2; mt++)
#pragma unroll
            for (int nt = 0; nt < 8; nt++) {
                const int col = n0 + wn * 64 + nt * 8 + tig * 2;
                float bx = 0.f, by = 0.f;
                if (bias) { bx = bias[col]; by = bias[col + 1]; }
#pragma unroll
                for (int h = 0; h < 2; h++) {
                    const int row = m0 + wm * 32 + mt * 16 + group + h * 8;
                    float v0 = alpha * acc[mt][nt][2 * h] + bx;
                    float v1 = alpha * acc[mt][nt][2 * h + 1] + by;
                    if (relu) { v0 = fmaxf(v0, 0.f); v1 = fmaxf(v1, 0.f); }
                    *(float2*)(C + (size_t)row * Nn + col) = make_float2(v0, v1);
                }
            }
    }
}

// ============================================================================
// band_logits_mma: CTA 64(M) x 128(N), BK=64, pre-split Q/K. Term-major MMA.
// ============================================================================
#define BL_AHI 0
#define BL_ALO (64 * PADR * 2)
#define BL_BHI (2 * 64 * PADR * 2)
#define BL_BLO (BL_BHI + 128 * PADR * 2)
#define BL_SMT (BL_BLO + 128 * PADR * 2)

__global__ void __launch_bounds__(256, 2)
band_logits_mma(const __nv_bfloat16* __restrict__ Qhi, const __nv_bfloat16* __restrict__ Qlo,
                const __nv_bfloat16* __restrict__ Khi, const __nv_bfloat16* __restrict__ Klo,
                float* __restrict__ band)
{
    extern __shared__ __align__(16) char smc[];
    const unsigned int sbase = smem_to_u32(smc);
    const int tid = threadIdx.x;
    const int lane = tid & 31;
    const int wid = tid >> 5;
    const int wm = wid & 1;
    const int wn = wid >> 1;
    const int i0 = blockIdx.y << 6;
    const int j0 = i0 - 256 + (blockIdx.x << 7);

    float acc[2][4][4];
#pragma unroll
    for (int i = 0; i < 2; i++)
#pragma unroll
        for (int j = 0; j < 4; j++)
#pragma unroll
            for (int c = 0; c < 4; c++) acc[i][j][c] = 0.f;

    const unsigned int a_off =
        (unsigned int)((wm * 32 + (lane & 15)) * PADR + ((lane >> 4) << 3)) * 2;
    const unsigned int b_off =
        (unsigned int)((wn * 32 + (lane & 7) + ((lane >> 4) << 3)) * PADR +
                       (((lane >> 3) & 1) << 3)) * 2;

    const int ar = tid >> 2;
    const int aq = (tid & 3) << 1;
    const int br = tid >> 1;
    const int bq = (tid & 1) << 2;
    const int jrow = j0 + br;
    const bool bok = (jrow >= 0) && (jrow < RTOT);
    const uint4 z4 = make_uint4(0, 0, 0, 0);

    for (int kc = 0; kc < DIM / 64; kc++) {
        const int k0 = kc * 64;
        __syncthreads();
        {
            const uint4* ah = (const uint4*)(Qhi + (size_t)(i0 + ar) * DIM + k0);
            const uint4* al = (const uint4*)(Qlo + (size_t)(i0 + ar) * DIM + k0);
#pragma unroll
            for (int j = 0; j < 2; j++) {
                const int q = aq + j;
                const int so = (ar * PADR + q * 8) * 2;
                *(uint4*)(smc + BL_AHI + so) = ah[q];
                *(uint4*)(smc + BL_ALO + so) = al[q];
            }
        }
        {
            const uint4* bh = (const uint4*)(Khi + (size_t)(bok ? jrow : 0) * DIM + k0);
            const uint4* bl = (const uint4*)(Klo + (size_t)(bok ? jrow : 0) * DIM + k0);
#pragma unroll
            for (int j = 0; j < 4; j++) {
                const int q = bq + j;
                const int so = (br * PADR + q * 8) * 2;
                *(uint4*)(smc + BL_BHI + so) = bok ? bh[q] : z4;
                *(uint4*)(smc + BL_BLO + so) = bok ? bl[q] : z4;
            }
        }
        __syncthreads();
#pragma unroll
        for (int ks = 0; ks < 4; ks++) {
            const unsigned int kb = (unsigned int)(ks * 16) * 2;
            unsigned int ahi[2][4], alo[2][4];
#pragma unroll
            for (int mt = 0; mt < 2; mt++) {
                const unsigned int ad = sbase + (unsigned int)(mt * 16 * PADR * 2) + a_off + kb;
                ldsm4(ahi[mt][0], ahi[mt][1], ahi[mt][2], ahi[mt][3], ad + BL_AHI);
                ldsm4(alo[mt][0], alo[mt][1], alo[mt][2], alo[mt][3], ad + BL_ALO);
            }
            unsigned int bhi[4][2], blo[4][2];
#pragma unroll
            for (int np = 0; np < 2; np++) {
                const unsigned int bd = sbase + (unsigned int)(np * 16 * PADR * 2) + b_off + kb;
                unsigned int r0, r1, r2, r3;
                ldsm4(r0, r1, r2, r3, bd + BL_BHI);
                bhi[2*np][0] = r0; bhi[2*np][1] = r1;
                bhi[2*np+1][0] = r2; bhi[2*np+1][1] = r3;
                ldsm4(r0, r1, r2, r3, bd + BL_BLO);
                blo[2*np][0] = r0; blo[2*np][1] = r1;
                blo[2*np+1][0] = r2; blo[2*np+1][1] = r3;
            }
            // term-major issue: 8 independent accs per term
#pragma unroll
            for (int mt = 0; mt < 2; mt++)
#pragma unroll
                for (int nt = 0; nt < 4; nt++)
                    mma16816(acc[mt][nt], ahi[mt][0], ahi[mt][1], ahi[mt][2], ahi[mt][3],
                             bhi[nt][0], bhi[nt][1]);
#pragma unroll
            for (int mt = 0; mt < 2; mt++)
#pragma unroll
                for (int nt = 0; nt < 4; nt++)
                    mma16816(acc[mt][nt], ahi[mt][0], ahi[mt][1], ahi[mt][2], ahi[mt][3],
                             blo[nt][0], blo[nt][1]);
#pragma unroll
            for (int mt = 0; mt < 2; mt++)
#pragma unroll
                for (int nt = 0; nt < 4; nt++)
                    mma16816(acc[mt][nt], alo[mt][0], alo[mt][1], alo[mt][2], alo[mt][3],
                             bhi[nt][0], bhi[nt][1]);
        }
    }

    const int group = lane >> 2, tig = lane & 3;
#pragma unroll
    for (int mt = 0; mt < 2; mt++)
#pragma unroll
        for (int nt = 0; nt < 4; nt++) {
            const int col = (blockIdx.x << 7) + wn * 32 + nt * 8 + tig * 2;
#pragma unroll
            for (int h = 0; h < 2; h++) {
                const int row = i0 + wm * 32 + mt * 16 + group + h * 8;
                *(float2*)(band + (size_t)row * BANDW + col) =
                    make_float2(acc[mt][nt][2 * h], acc[mt][nt][2 * h + 1]);
            }
        }
}

// ============================================================================
// band_apply_mma: Y[n,d] = sum_m w[m,n]*V[m,d]; V pre-split; fp32 out.
// w staged naturally [m][n]; A = w^T via ldmatrix.x4.trans. Term-major MMA.
// ============================================================================
#define BA_AHI 0
#define BA_ALO (64 * PADR * 2)
#define BA_BHI (2 * 64 * PADR * 2)
#define BA_BLO (3 * 64 * PADR * 2)
#define BA_SMT (4 * 64 * PADR * 2)

__global__ void __launch_bounds__(256, 2)
band_apply_mma(const float* __restrict__ band,
               const __nv_bfloat16* __restrict__ Vhi, const __nv_bfloat16* __restrict__ Vlo,
               float* __restrict__ Y)
{
    extern __shared__ __align__(16) char smc[];
    const unsigned int sbase = smem_to_u32(smc);
    const int tid = threadIdx.x;
    const int lane = tid & 31;
    const int wid = tid >> 5;
    const int wm = wid & 3;
    const int wn = wid >> 2;
    const int n0 = blockIdx.y << 6;
    const int d0 = blockIdx.x << 6;

    float acc[4][4];
#pragma unroll
    for (int j = 0; j < 4; j++)
#pragma unroll
        for (int c = 0; c < 4; c++) acc[j][c] = 0.f;

    const int atr = (lane & 7) + (((lane >> 4) & 1) << 3);
    const int atc = wm * 16 + (((lane >> 3) & 1) << 3);
    const int btr = (lane & 7) + (((lane >> 3) & 1) << 3);
    const int btc = (lane >> 4) << 3;

    const int r64 = tid >> 2;
    const int c4 = tid & 3;
    const uint4 z4 = make_uint4(0, 0, 0, 0);

    for (int ch = 0; ch < 9; ch++) {
        const int mb = n0 - 256 + (ch << 6);
        const int coff = 512 - (ch << 6);
        const int mrow = mb + r64;
        const bool ok = (mrow >= 0) && (mrow < RTOT);
        __syncthreads();
        {
            const float4* wp = (const float4*)(band + (size_t)(ok ? mrow : 0) * BANDW + coff);
#pragma unroll
            for (int j = 0; j < 4; j++) {
                const int q = c4 * 4 + j;
                float4 v = ok ? wp[q] : make_float4(0.f, 0.f, 0.f, 0.f);
                uint2 uh, ul;
                split4(v, uh, ul);
                const int so = (r64 * PADR + q * 4) * 2;
                *(uint2*)(smc + BA_AHI + so) = uh;
                *(uint2*)(smc + BA_ALO + so) = ul;
            }
        }
        {
            const uint4* vh = (const uint4*)(Vhi + (size_t)(ok ? mrow : 0) * DIM + d0);
            const uint4* vl = (const uint4*)(Vlo + (size_t)(ok ? mrow : 0) * DIM + d0);
#pragma unroll
            for (int j = 0; j < 2; j++) {
                const int q = c4 * 2 + j;
                const int so = (r64 * PADR + q * 8) * 2;
                *(uint4*)(smc + BA_BHI + so) = ok ? vh[q] : z4;
                *(uint4*)(smc + BA_BLO + so) = ok ? vl[q] : z4;
            }
        }
        __syncthreads();
#pragma unroll
        for (int ks = 0; ks < 4; ks++) {
            const int kk = ks * 16;
            unsigned int ahi[4], alo[4];
            {
                const unsigned int ad = sbase +
                    (unsigned int)((kk + atr) * PADR + atc) * 2;
                ldsm4t(ahi[0], ahi[1], ahi[2], ahi[3], ad + BA_AHI);
                ldsm4t(alo[0], alo[1], alo[2], alo[3], ad + BA_ALO);
            }
            unsigned int bhi[4][2], blo[4][2];
#pragma unroll
            for (int dh = 0; dh < 2; dh++) {
                const unsigned int bd = sbase +
                    (unsigned int)((kk + btr) * PADR + (wn * 32 + dh * 16 + btc)) * 2;
                unsigned int r0, r1, r2, r3;
                ldsm4t(r0, r1, r2, r3, bd + BA_BHI);
                bhi[2*dh][0] = r0; bhi[2*dh][1] = r1;
                bhi[2*dh+1][0] = r2; bhi[2*dh+1][1] = r3;
                ldsm4t(r0, r1, r2, r3, bd + BA_BLO);
                blo[2*dh][0] = r0; blo[2*dh][1] = r1;
                blo[2*dh+1][0] = r2; blo[2*dh+1][1] = r3;
            }
            // term-major issue: 4 independent accs per term
#pragma unroll
            for (int nt = 0; nt < 4; nt++)
                mma16816(acc[nt], ahi[0], ahi[1], ahi[2], ahi[3], bhi[nt][0], bhi[nt][1]);
#pragma unroll
            for (int nt = 0; nt < 4; nt++)
                mma16816(acc[nt], ahi[0], ahi[1], ahi[2], ahi[3], blo[nt][0], blo[nt][1]);
#pragma unroll
            for (int nt = 0; nt < 4; nt++)
                mma16816(acc[nt], alo[0], alo[1], alo[2], alo[3], bhi[nt][0], bhi[nt][1]);
        }
    }

    const int group = lane >> 2, tig = lane & 3;
#pragma unroll
    for (int nt = 0; nt < 4; nt++) {
        const int col = d0 + wn * 32 + nt * 8 + tig * 2;
#pragma unroll
        for (int h = 0; h < 2; h++) {
            const int row = n0 + wm * 16 + group + h * 8;
            *(float2*)(Y + (size_t)row * DIM + col) =
                make_float2(acc[nt][2 * h], acc[nt][2 * h + 1]);
        }
    }
}

// ---------------------------------------------------------------------------
// band_softmax: warp-shuffle reductions, 1 expf per element.
// ---------------------------------------------------------------------------
__global__ void band_softmax(float* __restrict__ band)
{
    __shared__ float red[8];
    const int i = blockIdx.x;
    const int tid = threadIdx.x;
    const int lane = tid & 31;
    const int wrp = tid >> 5;
    const int i0 = i & ~63;
    const int jstart = i0 - 256;
    const int bs = (i < SEQ) ? 0 : SEQ;
    const int jmin = max(i - 255, bs);
    const int jmax = min(i + 255, bs + SEQ - 1);
    const int cmin = jmin - jstart, cmax = jmax - jstart;
    float* row = band + (size_t)i * BANDW;

    const int c0 = tid, c1 = tid + 256, c2 = tid + 512;
    const bool ok2 = (c2 < BANDW);
    float v0 = -1e30f, v1 = -1e30f, v2 = -1e30f;
    if (c0 >= cmin && c0 <= cmax) v0 = row[c0];
    if (c1 >= cmin && c1 <= cmax) v1 = row[c1];
    if (ok2 && c2 >= cmin && c2 <= cmax) v2 = row[c2];

    float m = fmaxf(v0, fmaxf(v1, v2));
#pragma unroll
    for (int off = 16; off > 0; off >>= 1)
        m = fmaxf(m, __shfl_xor_sync(0xFFFFFFFFu, m, off));
    if (lane == 0) red[wrp] = m;
    __syncthreads();
    m = red[0];
#pragma unroll
    for (int w = 1; w < 8; w++) m = fmaxf(m, red[w]);
    __syncthreads();

    float e0 = (v0 > -1e29f) ? __expf(v0 - m) : 0.f;
    float e1 = (v1 > -1e29f) ? __expf(v1 - m) : 0.f;
    float e2 = (v2 > -1e29f) ? __expf(v2 - m) : 0.f;
    float s = e0 + e1 + e2;
#pragma unroll
    for (int off = 16; off > 0; off >>= 1)
        s += __shfl_xor_sync(0xFFFFFFFFu, s, off);
    if (lane == 0) red[wrp] = s;
    __syncthreads();
    s = red[0];
#pragma unroll
    for (int w = 1; w < 8; w++) s += red[w];
    const float inv = 1.f / s;

    row[c0] = e0 * inv;
    row[c1] = e1 * inv;
    if (ok2) row[c2] = e2 * inv;
}

// ---------------------------------------------------------------------------
__global__ void addln_acc(const float* __restrict__ A, const float* __restrict__ X,
                          const float* __restrict__ g, const float* __restrict__ bb,
                          float* __restrict__ ysum)
{
    __shared__ float red[256];
    const int row = blockIdx.x, tid = threadIdx.x;
    const size_t base = (size_t)row * DIM + tid * 4;
    float4 a = *(const float4*)(A + base);
    float4 x = *(const float4*)(X + base);
    float v0 = a.x + x.x, v1 = a.y + x.y, v2 = a.z + x.z, v3 = a.w + x.w;

    red[tid] = v0 + v1 + v2 + v3;
    __syncthreads();
    for (int s = 128; s > 0; s >>= 1) { if (tid < s) red[tid] += red[tid + s]; __syncthreads(); }
    const float mean = red[0] * (1.f / DIM);
    __syncthreads();

    const float d0 = v0 - mean, d1 = v1 - mean, d2 = v2 - mean, d3 = v3 - mean;
    red[tid] = d0 * d0 + d1 * d1 + d2 * d2 + d3 * d3;
    __syncthreads();
    for (int s = 128; s > 0; s >>= 1) { if (tid < s) red[tid] += red[tid + s]; __syncthreads(); }
    const float scale = 1.f / (sqrtf(red[0] * (1.f / (DIM - 1))) + LN_EPS);

    const int c = tid * 4;
    float4 gg = *(const float4*)(g + c);
    float4 bv = *(const float4*)(bb + c);
    float4 ys = *(float4*)(ysum + base);
    ys.x += gg.x * d0 * scale + bv.x;
    ys.y += gg.y * d1 * scale + bv.y;
    ys.z += gg.z * d2 * scale + bv.z;
    ys.w += gg.w * d3 * scale + bv.w;
    *(float4*)(ysum + base) = ys;
}

__global__ void ln_only(const float* __restrict__ H,
                        const float* __restrict__ g, const float* __restrict__ bb,
                        float* __restrict__ out)
{
    __shared__ float red[256];
    const int row = blockIdx.x, tid = threadIdx.x;
    const size_t base = (size_t)row * DIM + tid * 4;
    float4 h = *(const float4*)(H + base);
    red[tid] = h.x + h.y + h.z + h.w;
    __syncthreads();
    for (int s = 128; s > 0; s >>= 1) { if (tid < s) red[tid] += red[tid + s]; __syncthreads(); }
    const float mean = red[0] * (1.f / DIM);
    __syncthreads();

    const float d0 = h.x - mean, d1 = h.y - mean, d2 = h.z - mean, d3 = h.w - mean;
    red[tid] = d0 * d0 + d1 * d1 + d2 * d2 + d3 * d3;
    __syncthreads();
    for (int s = 128; s > 0; s >>= 1) { if (tid < s) red[tid] += red[tid + s]; __syncthreads(); }
    const float scale = 1.f / (sqrtf(red[0] * (1.f / (DIM - 1))) + LN_EPS);

    const int c = tid * 4;
    float4 gg = *(const float4*)(g + c);
    float4 bv = *(const float4*)(bb + c);
    float4 o;
    o.x = gg.x * d0 * scale + bv.x;
    o.y = gg.y * d1 * scale + bv.y;
    o.z = gg.z * d2 * scale + bv.z;
    o.w = gg.w * d3 * scale + bv.w;
    *(float4*)(out + base) = o;
}

__global__ void kd_dot(const float* __restrict__ H, const float* __restrict__ w,
                       const float* __restrict__ bias, float* __restrict__ out)
{
    __shared__ float red[256];
    const int row = blockIdx.x, tid = threadIdx.x;
    float4 h = *(const float4*)(H + (size_t)row * DIM + tid * 4);
    float4 ww = *(const float4*)(w + tid * 4);
    red[tid] = h.x * ww.x + h.y * ww.y + h.z * ww.z + h.w * ww.w;
    __syncthreads();
    for (int s = 128; s > 0; s >>= 1) { if (tid < s) red[tid] += red[tid + s]; __syncthreads(); }
    if (tid == 0) out[row] = red[0] + bias[0];
}

// ---------------------------------------------------------------------------
extern "C" void kernel_launch(void* const* d_in, const int* in_sizes, int n_in,
                              void* d_out, int out_size)
{
    (void)in_sizes; (void)n_in; (void)out_size;

    const float* x1   = (const float*)d_in[0];
    const float* x2   = (const float*)d_in[1];
    const float* x3   = (const float*)d_in[2];
    const float* Wk   = (const float*)d_in[3];
    const float* Wq   = (const float*)d_in[4];
    const float* Wv   = (const float*)d_in[5];
    const float* Wo   = (const float*)d_in[6];
    const float* ka_w = (const float*)d_in[7];
    const float* ka_b = (const float*)d_in[8];
    const float* kb_w = (const float*)d_in[9];
    const float* kb_b = (const float*)d_in[10];
    const float* kc_w = (const float*)d_in[11];
    const float* kc_b = (const float*)d_in[12];
    const float* kd_w = (const float*)d_in[13];
    const float* kd_b = (const float*)d_in[14];
    const float* g1   = (const float*)d_in[15];
    const float* b1   = (const float*)d_in[16];
    const float* g2   = (const float*)d_in[17];
    const float* b2   = (const float*)d_in[18];
    float* out = (float*)d_out;

    float* scratch = nullptr;
    cudaGetSymbolAddress((void**)&scratch, g_scratch);

    __nv_bfloat16* Khi[2]; __nv_bfloat16* Klo[2];
    __nv_bfloat16* Qhi[2]; __nv_bfloat16* Qlo[2];
    __nv_bfloat16* Vhi[2]; __nv_bfloat16* Vlo[2];
    float* bAp[2];
    for (int p = 0; p < 2; p++) {
        float* base = scratch + (size_t)p * 3 * RD;
        Khi[p] = (__nv_bfloat16*)(base);
        Klo[p] = (__nv_bfloat16*)(base + (size_t)RD / 2);
        Qhi[p] = (__nv_bfloat16*)(base + (size_t)RD);
        Qlo[p] = (__nv_bfloat16*)(base + (size_t)RD * 3 / 2);
        Vhi[p] = (__nv_bfloat16*)(base + (size_t)RD * 2);
        Vlo[p] = (__nv_bfloat16*)(base + (size_t)RD * 5 / 2);
        bAp[p] = scratch + (size_t)RD * 6 + (size_t)p * RD;
    }
    float* ySum  = scratch + (size_t)RD * 8;
    float* woOut = scratch + (size_t)RD * 9;
    float* band  = scratch + (size_t)RD * 10;

    static cudaStream_t sA = nullptr, sB = nullptr, sC = nullptr;
    static cudaEvent_t e0, eD, eK[3], eQ[3], eV[3], eBL[3], eBA[3], eWo[3];
    if (sA == nullptr) {
        cudaStreamCreateWithFlags(&sA, cudaStreamNonBlocking);
        cudaStreamCreateWithFlags(&sB, cudaStreamNonBlocking);
        cudaStreamCreateWithFlags(&sC, cudaStreamNonBlocking);
        cudaEventCreateWithFlags(&e0, cudaEventDisableTiming);
        cudaEventCreateWithFlags(&eD, cudaEventDisableTiming);
        for (int t = 0; t < 3; t++) {
            cudaEventCreateWithFlags(&eK[t], cudaEventDisableTiming);
            cudaEventCreateWithFlags(&eQ[t], cudaEventDisableTiming);
            cudaEventCreateWithFlags(&eV[t], cudaEventDisableTiming);
            cudaEventCreateWithFlags(&eBL[t], cudaEventDisableTiming);
            cudaEventCreateWithFlags(&eBA[t], cudaEventDisableTiming);
            cudaEventCreateWithFlags(&eWo[t], cudaEventDisableTiming);
        }
    }

    cudaFuncSetAttribute(tgemm, cudaFuncAttributeMaxDynamicSharedMemorySize, SMT);
    cudaFuncSetAttribute(band_logits_mma, cudaFuncAttributeMaxDynamicSharedMemorySize, BL_SMT);
    cudaFuncSetAttribute(band_apply_mma, cudaFuncAttributeMaxDynamicSharedMemorySize, BA_SMT);

    const dim3 gT(DIM / 128, RTOT / 128);
    const dim3 gL(BANDW / 128, RTOT / 64);
    const dim3 gA(DIM / 64, RTOT / 64);
    const cudaStream_t s0 = 0;
    const float* xs[3] = {x1, x2, x3};

    cudaMemsetAsync(ySum, 0, sizeof(float) * (size_t)RD, s0);
    cudaEventRecord(e0, s0);

    // Prelaunch K/Q/V for towers 0 and 1.
    for (int t = 0; t < 2; t++) {
        const int p = t & 1;
        cudaStreamWaitEvent(sA, e0, 0);
        tgemm<<<gT, 256, SMT, sA>>>(xs[t], Wk, nullptr, nullptr, Khi[p], Klo[p], DIM, 1.0f, 0);
        cudaEventRecord(eK[t], sA);
        cudaStreamWaitEvent(sB, e0, 0);
        tgemm<<<gT, 256, SMT, sB>>>(xs[t], Wq, nullptr, nullptr, Qhi[p], Qlo[p], DIM, 0.06f, 0);
        cudaEventRecord(eQ[t], sB);
        cudaStreamWaitEvent(sC, e0, 0);
        tgemm<<<gT, 256, SMT, sC>>>(xs[t], Wv, nullptr, nullptr, Vhi[p], Vlo[p], DIM, 1.0f, 0);
        cudaEventRecord(eV[t], sC);
    }

    for (int t = 0; t < 3; t++) {
        const float* x = xs[t];
        const int p = t & 1;

        cudaStreamWaitEvent(s0, eK[t], 0);
        cudaStreamWaitEvent(s0, eQ[t], 0);
        band_logits_mma<<<gL, 256, BL_SMT, s0>>>(Qhi[p], Qlo[p], Khi[p], Klo[p], band);
        cudaEventRecord(eBL[t], s0);

        if (t + 2 < 3) {
            const int p2 = (t + 2) & 1;
            cudaStreamWaitEvent(sA, eBL[t], 0);
            tgemm<<<gT, 256, SMT, sA>>>(xs[t + 2], Wk, nullptr, nullptr, Khi[p2], Klo[p2], DIM, 1.0f, 0);
            cudaEventRecord(eK[t + 2], sA);
            cudaStreamWaitEvent(sB, eBL[t], 0);
            tgemm<<<gT, 256, SMT, sB>>>(xs[t + 2], Wq, nullptr, nullptr, Qhi[p2], Qlo[p2], DIM, 0.06f, 0);
            cudaEventRecord(eQ[t + 2], sB);
        }

        band_softmax<<<RTOT, 256, 0, s0>>>(band);
        cudaStreamWaitEvent(s0, eV[t], 0);
        if (t >= 2) cudaStreamWaitEvent(s0, eWo[t - 2], 0);
        band_apply_mma<<<gA, 256, BA_SMT, s0>>>(band, Vhi[p], Vlo[p], bAp[p]);
        cudaEventRecord(eBA[t], s0);

        if (t + 2 < 3) {
            const int p2 = (t + 2) & 1;
            cudaStreamWaitEvent(sC, eBA[t], 0);
            tgemm<<<gT, 256, SMT, sC>>>(xs[t + 2], Wv, nullptr, nullptr, Vhi[p2], Vlo[p2], DIM, 1.0f, 0);
            cudaEventRecord(eV[t + 2], sC);
        }

        cudaStreamWaitEvent(sC, eBA[t], 0);
        tgemm<<<gT, 256, SMT, sC>>>(bAp[p], Wo, nullptr, woOut, nullptr, nullptr, DIM, 1.0f, 0);
        cudaEventRecord(eWo[t], sC);
        addln_acc<<<RTOT, 256, 0, sC>>>(woOut, x, g1, b1, ySum);
    }
    cudaEventRecord(eD, sC);

    // MLP chain on s0
    cudaStreamWaitEvent(s0, eD, 0);
    tgemm<<<gT, 256, SMT, s0>>>(ySum, ka_w, ka_b, bAp[0], nullptr, nullptr, DIM, 1.0f, 0);
    tgemm<<<gT, 256, SMT, s0>>>(bAp[0], kb_w, kb_b, woOut, nullptr, nullptr, DIM, 1.0f, 0);
    tgemm<<<gT, 256, SMT, s0>>>(woOut, kc_w, kc_b, bAp[0], nullptr, nullptr, DIM, 1.0f, 1);
    ln_only<<<RTOT, 256, 0, s0>>>(bAp[0], g2, b2, woOut);
    kd_dot<<<RTOT, 256, 0, s0>>>(woOut, kd_w, kd_b, out);
}

// round 17
// speedup vs baseline: 1.0175x; 1.0175x over previous
#include <cuda_runtime.h>
#include <cuda_bf16.h>
#include <cstdint>
#include <math.h>

#define RTOT  8192              // B*N rows
#define SEQ   4096              // per-batch sequence length
#define DIM   1024
#define BANDW 640               // padded band width per row-block
#define LN_EPS 1e-6f
#define RD (RTOT * DIM)
#define BANDE ((size_t)RTOT * BANDW)

// Scratch (float units):
//  parity p in {0,1}: K/Q/V split-plane pairs (3*RD floats per parity)
//  [6RD, 8RD)   bA0, bA1 (parity)
//  [8RD, 9RD)   ySum
//  [9RD, 10RD)  woOut
//  [10RD, ...)  band
__device__ float g_scratch[10 * RD + BANDE];

// ============================================================================
// mma.sync helpers
// ============================================================================
__device__ __forceinline__ unsigned int smem_to_u32(const void* p) {
    unsigned int a;
    asm("{ .reg .u64 t; cvta.to.shared.u64 t, %1; cvt.u32.u64 %0, t; }"
        : "=r"(a) : "l"(p));
    return a;
}

__device__ __forceinline__ void ldsm4(unsigned int& r0, unsigned int& r1,
                                      unsigned int& r2, unsigned int& r3,
                                      unsigned int addr) {
    asm volatile("ldmatrix.sync.aligned.m8n8.x4.shared.b16 {%0,%1,%2,%3}, [%4];"
                 : "=r"(r0), "=r"(r1), "=r"(r2), "=r"(r3) : "r"(addr));
}
__device__ __forceinline__ void ldsm4t(unsigned int& r0, unsigned int& r1,
                                       unsigned int& r2, unsigned int& r3,
                                       unsigned int addr) {
    asm volatile("ldmatrix.sync.aligned.m8n8.x4.trans.shared.b16 {%0,%1,%2,%3}, [%4];"
                 : "=r"(r0), "=r"(r1), "=r"(r2), "=r"(r3) : "r"(addr));
}

__device__ __forceinline__ void mma16816(float* c, unsigned int a0, unsigned int a1,
                                         unsigned int a2, unsigned int a3,
                                         unsigned int b0, unsigned int b1) {
    asm volatile(
        "mma.sync.aligned.m16n8k16.row.col.f32.bf16.bf16.f32 "
        "{%0,%1,%2,%3}, {%4,%5,%6,%7}, {%8,%9}, {%0,%1,%2,%3};"
        : "+f"(c[0]), "+f"(c[1]), "+f"(c[2]), "+f"(c[3])
        : "r"(a0), "r"(a1), "r"(a2), "r"(a3), "r"(b0), "r"(b1));
}

__device__ __forceinline__ unsigned short bfu(float f) {
    return __bfloat16_as_ushort(__float2bfloat16(f));
}
__device__ __forceinline__ float bff(unsigned short u) {
    return __bfloat162float(__ushort_as_bfloat16(u));
}

__device__ __forceinline__ void split4(float4 v, uint2& uh, uint2& ul) {
    unsigned short hx = bfu(v.x), hy = bfu(v.y), hz = bfu(v.z), hw = bfu(v.w);
    uh = make_uint2((unsigned int)hx | ((unsigned int)hy << 16),
                    (unsigned int)hz | ((unsigned int)hw << 16));
    unsigned short lx = bfu(v.x - bff(hx)), ly = bfu(v.y - bff(hy));
    unsigned short lz = bfu(v.z - bff(hz)), lw = bfu(v.w - bff(hw));
    ul = make_uint2((unsigned int)lx | ((unsigned int)ly << 16),
                    (unsigned int)lz | ((unsigned int)lw << 16));
}

// ============================================================================
// tgemm: acc = alpha*(A[M,1024] @ B[Nn,1024]^T).
//   Chi/Clo non-null -> split bf16 planes; else fp32 C (+bias)(+relu)
// CTA 128x128, BK=64, 8 warps (4M x 2N), bf16-split-3, term-major MMA.
// ============================================================================
#define PADR 72
#define TILE_B (128 * PADR * 2)
#define OFF_AHI 0
#define OFF_ALO (1 * TILE_B)
#define OFF_BHI (2 * TILE_B)
#define OFF_BLO (3 * TILE_B)
#define SMT     (4 * TILE_B)

__global__ void __launch_bounds__(256, 2)
tgemm(const float* __restrict__ A, const float* __restrict__ B,
      const float* __restrict__ bias, float* __restrict__ C,
      __nv_bfloat16* __restrict__ Chi, __nv_bfloat16* __restrict__ Clo,
      int Nn, float alpha, int relu)
{
    extern __shared__ __align__(16) char smc[];
    const unsigned int sbase = smem_to_u32(smc);
    const int tid = threadIdx.x;
    const int lane = tid & 31;
    const int wid = tid >> 5;
    const int wm = wid & 3;
    const int wn = wid >> 2;
    const int m0 = blockIdx.y << 7;
    const int n0 = blockIdx.x << 7;

    float acc[2][8][4];
#pragma unroll
    for (int i = 0; i < 2; i++)
#pragma unroll
        for (int j = 0; j < 8; j++)
#pragma unroll
            for (int c = 0; c < 4; c++) acc[i][j][c] = 0.f;

    const int lrow = tid >> 2;
    const int lseg = (tid & 3) << 2;

    const unsigned int a_off =
        (unsigned int)((wm * 32 + (lane & 15)) * PADR + ((lane >> 4) << 3)) * 2;
    const unsigned int b_off =
        (unsigned int)((wn * 64 + (lane & 7) + ((lane >> 4) << 3)) * PADR +
                       (((lane >> 3) & 1) << 3)) * 2;

    for (int kc = 0; kc < DIM / 64; kc++) {
        const int k0 = kc * 64;
        __syncthreads();
#pragma unroll
        for (int half = 0; half < 2; half++) {
            const int r = lrow + half * 64;
            const float4* ap = (const float4*)(A + (size_t)(m0 + r) * DIM + k0);
            const float4* bp = (const float4*)(B + (size_t)(n0 + r) * DIM + k0);
#pragma unroll
            for (int j = 0; j < 4; j++) {
                const int q = lseg + j;
                uint2 uh, ul;
                split4(ap[q], uh, ul);
                const int so = (r * PADR + q * 4) * 2;
                *(uint2*)(smc + OFF_AHI + so) = uh;
                *(uint2*)(smc + OFF_ALO + so) = ul;
                split4(bp[q], uh, ul);
                *(uint2*)(smc + OFF_BHI + so) = uh;
                *(uint2*)(smc + OFF_BLO + so) = ul;
            }
        }
        __syncthreads();
#pragma unroll
        for (int ks = 0; ks < 4; ks++) {
            const unsigned int kb = (unsigned int)(ks * 16) * 2;
            unsigned int ahi[2][4], alo[2][4];
#pragma unroll
            for (int mt = 0; mt < 2; mt++) {
                const unsigned int ad = sbase + (unsigned int)(mt * 16 * PADR * 2) + a_off + kb;
                ldsm4(ahi[mt][0], ahi[mt][1], ahi[mt][2], ahi[mt][3], ad + OFF_AHI);
                ldsm4(alo[mt][0], alo[mt][1], alo[mt][2], alo[mt][3], ad + OFF_ALO);
            }
            unsigned int bhi[8][2], blo[8][2];
#pragma unroll
            for (int np = 0; np < 4; np++) {
                const unsigned int bd = sbase + (unsigned int)(np * 16 * PADR * 2) + b_off + kb;
                unsigned int r0, r1, r2, r3;
                ldsm4(r0, r1, r2, r3, bd + OFF_BHI);
                bhi[2*np][0] = r0; bhi[2*np][1] = r1;
                bhi[2*np+1][0] = r2; bhi[2*np+1][1] = r3;
                ldsm4(r0, r1, r2, r3, bd + OFF_BLO);
                blo[2*np][0] = r0; blo[2*np][1] = r1;
                blo[2*np+1][0] = r2; blo[2*np+1][1] = r3;
            }
#pragma unroll
            for (int mt = 0; mt < 2; mt++)
#pragma unroll
                for (int nt = 0; nt < 8; nt++)
                    mma16816(acc[mt][nt], ahi[mt][0], ahi[mt][1], ahi[mt][2], ahi[mt][3],
                             bhi[nt][0], bhi[nt][1]);
#pragma unroll
            for (int mt = 0; mt < 2; mt++)
#pragma unroll
                for (int nt = 0; nt < 8; nt++)
                    mma16816(acc[mt][nt], ahi[mt][0], ahi[mt][1], ahi[mt][2], ahi[mt][3],
                             blo[nt][0], blo[nt][1]);
#pragma unroll
            for (int mt = 0; mt < 2; mt++)
#pragma unroll
                for (int nt = 0; nt < 8; nt++)
                    mma16816(acc[mt][nt], alo[mt][0], alo[mt][1], alo[mt][2], alo[mt][3],
                             bhi[nt][0], bhi[nt][1]);
        }
    }

    const int group = lane >> 2, tig = lane & 3;
    if (Chi) {
#pragma unroll
        for (int mt = 0; mt < 2; mt++)
#pragma unroll
            for (int nt = 0; nt < 8; nt++) {
                const int col = n0 + wn * 64 + nt * 8 + tig * 2;
#pragma unroll
                for (int h = 0; h < 2; h++) {
                    const int row = m0 + wm * 32 + mt * 16 + group + h * 8;
                    float v0 = alpha * acc[mt][nt][2 * h];
                    float v1 = alpha * acc[mt][nt][2 * h + 1];
                    unsigned short h0 = bfu(v0), h1 = bfu(v1);
                    unsigned short l0 = bfu(v0 - bff(h0)), l1 = bfu(v1 - bff(h1));
                    const size_t o = (size_t)row * Nn + col;
                    *(unsigned int*)(Chi + o) = (unsigned int)h0 | ((unsigned int)h1 << 16);
                    *(unsigned int*)(Clo + o) = (unsigned int)l0 | ((unsigned int)l1 << 16);
                }
            }
    } else {
#pragma unroll
        for (int mt = 0; mt < 2; mt++)
#pragma unroll
            for (int nt = 0; nt < 8; nt++) {
                const int col = n0 + wn * 64 + nt * 8 + tig * 2;
                float bx = 0.f, by = 0.f;
                if (bias) { bx = bias[col]; by = bias[col + 1]; }
#pragma unroll
                for (int h = 0; h < 2; h++) {
                    const int row = m0 + wm * 32 + mt * 16 + group + h * 8;
                    float v0 = alpha * acc[mt][nt][2 * h] + bx;
                    float v1 = alpha * acc[mt][nt][2 * h + 1] + by;
                    if (relu) { v0 = fmaxf(v0, 0.f); v1 = fmaxf(v1, 0.f); }
                    *(float2*)(C + (size_t)row * Nn + col) = make_float2(v0, v1);
                }
            }
    }
}

// ============================================================================
// band_logits_mma: CTA 64(M) x 128(N), BK=64, pre-split Q/K.
// ============================================================================
#define BL_AHI 0
#define BL_ALO (64 * PADR * 2)
#define BL_BHI (2 * 64 * PADR * 2)
#define BL_BLO (BL_BHI + 128 * PADR * 2)
#define BL_SMT (BL_BLO + 128 * PADR * 2)

__global__ void __launch_bounds__(256, 2)
band_logits_mma(const __nv_bfloat16* __restrict__ Qhi, const __nv_bfloat16* __restrict__ Qlo,
                const __nv_bfloat16* __restrict__ Khi, const __nv_bfloat16* __restrict__ Klo,
                float* __restrict__ band)
{
    extern __shared__ __align__(16) char smc[];
    const unsigned int sbase = smem_to_u32(smc);
    const int tid = threadIdx.x;
    const int lane = tid & 31;
    const int wid = tid >> 5;
    const int wm = wid & 1;
    const int wn = wid >> 1;
    const int i0 = blockIdx.y << 6;
    const int j0 = i0 - 256 + (blockIdx.x << 7);

    float acc[2][4][4];
#pragma unroll
    for (int i = 0; i < 2; i++)
#pragma unroll
        for (int j = 0; j < 4; j++)
#pragma unroll
            for (int c = 0; c < 4; c++) acc[i][j][c] = 0.f;

    const unsigned int a_off =
        (unsigned int)((wm * 32 + (lane & 15)) * PADR + ((lane >> 4) << 3)) * 2;
    const unsigned int b_off =
        (unsigned int)((wn * 32 + (lane & 7) + ((lane >> 4) << 3)) * PADR +
                       (((lane >> 3) & 1) << 3)) * 2;

    const int ar = tid >> 2;
    const int aq = (tid & 3) << 1;
    const int br = tid >> 1;
    const int bq = (tid & 1) << 2;
    const int jrow = j0 + br;
    const bool bok = (jrow >= 0) && (jrow < RTOT);
    const uint4 z4 = make_uint4(0, 0, 0, 0);

    for (int kc = 0; kc < DIM / 64; kc++) {
        const int k0 = kc * 64;
        __syncthreads();
        {
            const uint4* ah = (const uint4*)(Qhi + (size_t)(i0 + ar) * DIM + k0);
            const uint4* al = (const uint4*)(Qlo + (size_t)(i0 + ar) * DIM + k0);
#pragma unroll
            for (int j = 0; j < 2; j++) {
                const int q = aq + j;
                const int so = (ar * PADR + q * 8) * 2;
                *(uint4*)(smc + BL_AHI + so) = ah[q];
                *(uint4*)(smc + BL_ALO + so) = al[q];
            }
        }
        {
            const uint4* bh = (const uint4*)(Khi + (size_t)(bok ? jrow : 0) * DIM + k0);
            const uint4* bl = (const uint4*)(Klo + (size_t)(bok ? jrow : 0) * DIM + k0);
#pragma unroll
            for (int j = 0; j < 4; j++) {
                const int q = bq + j;
                const int so = (br * PADR + q * 8) * 2;
                *(uint4*)(smc + BL_BHI + so) = bok ? bh[q] : z4;
                *(uint4*)(smc + BL_BLO + so) = bok ? bl[q] : z4;
            }
        }
        __syncthreads();
#pragma unroll
        for (int ks = 0; ks < 4; ks++) {
            const unsigned int kb = (unsigned int)(ks * 16) * 2;
            unsigned int ahi[2][4], alo[2][4];
#pragma unroll
            for (int mt = 0; mt < 2; mt++) {
                const unsigned int ad = sbase + (unsigned int)(mt * 16 * PADR * 2) + a_off + kb;
                ldsm4(ahi[mt][0], ahi[mt][1], ahi[mt][2], ahi[mt][3], ad + BL_AHI);
                ldsm4(alo[mt][0], alo[mt][1], alo[mt][2], alo[mt][3], ad + BL_ALO);
            }
            unsigned int bhi[4][2], blo[4][2];
#pragma unroll
            for (int np = 0; np < 2; np++) {
                const unsigned int bd = sbase + (unsigned int)(np * 16 * PADR * 2) + b_off + kb;
                unsigned int r0, r1, r2, r3;
                ldsm4(r0, r1, r2, r3, bd + BL_BHI);
                bhi[2*np][0] = r0; bhi[2*np][1] = r1;
                bhi[2*np+1][0] = r2; bhi[2*np+1][1] = r3;
                ldsm4(r0, r1, r2, r3, bd + BL_BLO);
                blo[2*np][0] = r0; blo[2*np][1] = r1;
                blo[2*np+1][0] = r2; blo[2*np+1][1] = r3;
            }
#pragma unroll
            for (int mt = 0; mt < 2; mt++)
#pragma unroll
                for (int nt = 0; nt < 4; nt++)
                    mma16816(acc[mt][nt], ahi[mt][0], ahi[mt][1], ahi[mt][2], ahi[mt][3],
                             bhi[nt][0], bhi[nt][1]);
#pragma unroll
            for (int mt = 0; mt < 2; mt++)
#pragma unroll
                for (int nt = 0; nt < 4; nt++)
                    mma16816(acc[mt][nt], ahi[mt][0], ahi[mt][1], ahi[mt][2], ahi[mt][3],
                             blo[nt][0], blo[nt][1]);
#pragma unroll
            for (int mt = 0; mt < 2; mt++)
#pragma unroll
                for (int nt = 0; nt < 4; nt++)
                    mma16816(acc[mt][nt], alo[mt][0], alo[mt][1], alo[mt][2], alo[mt][3],
                             bhi[nt][0], bhi[nt][1]);
        }
    }

    const int group = lane >> 2, tig = lane & 3;
#pragma unroll
    for (int mt = 0; mt < 2; mt++)
#pragma unroll
        for (int nt = 0; nt < 4; nt++) {
            const int col = (blockIdx.x << 7) + wn * 32 + nt * 8 + tig * 2;
#pragma unroll
            for (int h = 0; h < 2; h++) {
                const int row = i0 + wm * 32 + mt * 16 + group + h * 8;
                *(float2*)(band + (size_t)row * BANDW + col) =
                    make_float2(acc[mt][nt][2 * h], acc[mt][nt][2 * h + 1]);
            }
        }
}

// ============================================================================
// band_apply_mma: Y[n,d] = sum_m w[m,n]*V[m,d]; V pre-split; fp32 out.
// w staged naturally [m][n]; A = w^T via ldmatrix.x4.trans.
// ============================================================================
#define BA_AHI 0
#define BA_ALO (64 * PADR * 2)
#define BA_BHI (2 * 64 * PADR * 2)
#define BA_BLO (3 * 64 * PADR * 2)
#define BA_SMT (4 * 64 * PADR * 2)

__global__ void __launch_bounds__(256, 2)
band_apply_mma(const float* __restrict__ band,
               const __nv_bfloat16* __restrict__ Vhi, const __nv_bfloat16* __restrict__ Vlo,
               float* __restrict__ Y)
{
    extern __shared__ __align__(16) char smc[];
    const unsigned int sbase = smem_to_u32(smc);
    const int tid = threadIdx.x;
    const int lane = tid & 31;
    const int wid = tid >> 5;
    const int wm = wid & 3;
    const int wn = wid >> 2;
    const int n0 = blockIdx.y << 6;
    const int d0 = blockIdx.x << 6;

    float acc[4][4];
#pragma unroll
    for (int j = 0; j < 4; j++)
#pragma unroll
        for (int c = 0; c < 4; c++) acc[j][c] = 0.f;

    const int atr = (lane & 7) + (((lane >> 4) & 1) << 3);
    const int atc = wm * 16 + (((lane >> 3) & 1) << 3);
    const int btr = (lane & 7) + (((lane >> 3) & 1) << 3);
    const int btc = (lane >> 4) << 3;

    const int r64 = tid >> 2;
    const int c4 = tid & 3;
    const uint4 z4 = make_uint4(0, 0, 0, 0);

    for (int ch = 0; ch < 9; ch++) {
        const int mb = n0 - 256 + (ch << 6);
        const int coff = 512 - (ch << 6);
        const int mrow = mb + r64;
        const bool ok = (mrow >= 0) && (mrow < RTOT);
        __syncthreads();
        {
            const float4* wp = (const float4*)(band + (size_t)(ok ? mrow : 0) * BANDW + coff);
#pragma unroll
            for (int j = 0; j < 4; j++) {
                const int q = c4 * 4 + j;
                float4 v = ok ? wp[q] : make_float4(0.f, 0.f, 0.f, 0.f);
                uint2 uh, ul;
                split4(v, uh, ul);
                const int so = (r64 * PADR + q * 4) * 2;
                *(uint2*)(smc + BA_AHI + so) = uh;
                *(uint2*)(smc + BA_ALO + so) = ul;
            }
        }
        {
            const uint4* vh = (const uint4*)(Vhi + (size_t)(ok ? mrow : 0) * DIM + d0);
            const uint4* vl = (const uint4*)(Vlo + (size_t)(ok ? mrow : 0) * DIM + d0);
#pragma unroll
            for (int j = 0; j < 2; j++) {
                const int q = c4 * 2 + j;
                const int so = (r64 * PADR + q * 8) * 2;
                *(uint4*)(smc + BA_BHI + so) = ok ? vh[q] : z4;
                *(uint4*)(smc + BA_BLO + so) = ok ? vl[q] : z4;
            }
        }
        __syncthreads();
#pragma unroll
        for (int ks = 0; ks < 4; ks++) {
            const int kk = ks * 16;
            unsigned int ahi[4], alo[4];
            {
                const unsigned int ad = sbase +
                    (unsigned int)((kk + atr) * PADR + atc) * 2;
                ldsm4t(ahi[0], ahi[1], ahi[2], ahi[3], ad + BA_AHI);
                ldsm4t(alo[0], alo[1], alo[2], alo[3], ad + BA_ALO);
            }
            unsigned int bhi[4][2], blo[4][2];
#pragma unroll
            for (int dh = 0; dh < 2; dh++) {
                const unsigned int bd = sbase +
                    (unsigned int)((kk + btr) * PADR + (wn * 32 + dh * 16 + btc)) * 2;
                unsigned int r0, r1, r2, r3;
                ldsm4t(r0, r1, r2, r3, bd + BA_BHI);
                bhi[2*dh][0] = r0; bhi[2*dh][1] = r1;
                bhi[2*dh+1][0] = r2; bhi[2*dh+1][1] = r3;
                ldsm4t(r0, r1, r2, r3, bd + BA_BLO);
                blo[2*dh][0] = r0; blo[2*dh][1] = r1;
                blo[2*dh+1][0] = r2; blo[2*dh+1][1] = r3;
            }
#pragma unroll
            for (int nt = 0; nt < 4; nt++)
                mma16816(acc[nt], ahi[0], ahi[1], ahi[2], ahi[3], bhi[nt][0], bhi[nt][1]);
#pragma unroll
            for (int nt = 0; nt < 4; nt++)
                mma16816(acc[nt], ahi[0], ahi[1], ahi[2], ahi[3], blo[nt][0], blo[nt][1]);
#pragma unroll
            for (int nt = 0; nt < 4; nt++)
                mma16816(acc[nt], alo[0], alo[1], alo[2], alo[3], bhi[nt][0], bhi[nt][1]);
        }
    }

    const int group = lane >> 2, tig = lane & 3;
#pragma unroll
    for (int nt = 0; nt < 4; nt++) {
        const int col = d0 + wn * 32 + nt * 8 + tig * 2;
#pragma unroll
        for (int h = 0; h < 2; h++) {
            const int row = n0 + wm * 16 + group + h * 8;
            *(float2*)(Y + (size_t)row * DIM + col) =
                make_float2(acc[nt][2 * h], acc[nt][2 * h + 1]);
        }
    }
}

// ---------------------------------------------------------------------------
// band_softmax: warp-shuffle reductions, 1 expf per element.
// ---------------------------------------------------------------------------
__global__ void band_softmax(float* __restrict__ band)
{
    __shared__ float red[8];
    const int i = blockIdx.x;
    const int tid = threadIdx.x;
    const int lane = tid & 31;
    const int wrp = tid >> 5;
    const int i0 = i & ~63;
    const int jstart = i0 - 256;
    const int bs = (i < SEQ) ? 0 : SEQ;
    const int jmin = max(i - 255, bs);
    const int jmax = min(i + 255, bs + SEQ - 1);
    const int cmin = jmin - jstart, cmax = jmax - jstart;
    float* row = band + (size_t)i * BANDW;

    const int c0 = tid, c1 = tid + 256, c2 = tid + 512;
    const bool ok2 = (c2 < BANDW);
    float v0 = -1e30f, v1 = -1e30f, v2 = -1e30f;
    if (c0 >= cmin && c0 <= cmax) v0 = row[c0];
    if (c1 >= cmin && c1 <= cmax) v1 = row[c1];
    if (ok2 && c2 >= cmin && c2 <= cmax) v2 = row[c2];

    float m = fmaxf(v0, fmaxf(v1, v2));
#pragma unroll
    for (int off = 16; off > 0; off >>= 1)
        m = fmaxf(m, __shfl_xor_sync(0xFFFFFFFFu, m, off));
    if (lane == 0) red[wrp] = m;
    __syncthreads();
    m = red[0];
#pragma unroll
    for (int w = 1; w < 8; w++) m = fmaxf(m, red[w]);
    __syncthreads();

    float e0 = (v0 > -1e29f) ? __expf(v0 - m) : 0.f;
    float e1 = (v1 > -1e29f) ? __expf(v1 - m) : 0.f;
    float e2 = (v2 > -1e29f) ? __expf(v2 - m) : 0.f;
    float s = e0 + e1 + e2;
#pragma unroll
    for (int off = 16; off > 0; off >>= 1)
        s += __shfl_xor_sync(0xFFFFFFFFu, s, off);
    if (lane == 0) red[wrp] = s;
    __syncthreads();
    s = red[0];
#pragma unroll
    for (int w = 1; w < 8; w++) s += red[w];
    const float inv = 1.f / s;

    row[c0] = e0 * inv;
    row[c1] = e1 * inv;
    if (ok2) row[c2] = e2 * inv;
}

// ---------------------------------------------------------------------------
__global__ void addln_acc(const float* __restrict__ A, const float* __restrict__ X,
                          const float* __restrict__ g, const float* __restrict__ bb,
                          float* __restrict__ ysum)
{
    __shared__ float red[256];
    const int row = blockIdx.x, tid = threadIdx.x;
    const size_t base = (size_t)row * DIM + tid * 4;
    float4 a = *(const float4*)(A + base);
    float4 x = *(const float4*)(X + base);
    float v0 = a.x + x.x, v1 = a.y + x.y, v2 = a.z + x.z, v3 = a.w + x.w;

    red[tid] = v0 + v1 + v2 + v3;
    __syncthreads();
    for (int s = 128; s > 0; s >>= 1) { if (tid < s) red[tid] += red[tid + s]; __syncthreads(); }
    const float mean = red[0] * (1.f / DIM);
    __syncthreads();

    const float d0 = v0 - mean, d1 = v1 - mean, d2 = v2 - mean, d3 = v3 - mean;
    red[tid] = d0 * d0 + d1 * d1 + d2 * d2 + d3 * d3;
    __syncthreads();
    for (int s = 128; s > 0; s >>= 1) { if (tid < s) red[tid] += red[tid + s]; __syncthreads(); }
    const float scale = 1.f / (sqrtf(red[0] * (1.f / (DIM - 1))) + LN_EPS);

    const int c = tid * 4;
    float4 gg = *(const float4*)(g + c);
    float4 bv = *(const float4*)(bb + c);
    float4 ys = *(float4*)(ysum + base);
    ys.x += gg.x * d0 * scale + bv.x;
    ys.y += gg.y * d1 * scale + bv.y;
    ys.z += gg.z * d2 * scale + bv.z;
    ys.w += gg.w * d3 * scale + bv.w;
    *(float4*)(ysum + base) = ys;
}

__global__ void ln_only(const float* __restrict__ H,
                        const float* __restrict__ g, const float* __restrict__ bb,
                        float* __restrict__ out)
{
    __shared__ float red[256];
    const int row = blockIdx.x, tid = threadIdx.x;
    const size_t base = (size_t)row * DIM + tid * 4;
    float4 h = *(const float4*)(H + base);
    red[tid] = h.x + h.y + h.z + h.w;
    __syncthreads();
    for (int s = 128; s > 0; s >>= 1) { if (tid < s) red[tid] += red[tid + s]; __syncthreads(); }
    const float mean = red[0] * (1.f / DIM);
    __syncthreads();

    const float d0 = h.x - mean, d1 = h.y - mean, d2 = h.z - mean, d3 = h.w - mean;
    red[tid] = d0 * d0 + d1 * d1 + d2 * d2 + d3 * d3;
    __syncthreads();
    for (int s = 128; s > 0; s >>= 1) { if (tid < s) red[tid] += red[tid + s]; __syncthreads(); }
    const float scale = 1.f / (sqrtf(red[0] * (1.f / (DIM - 1))) + LN_EPS);

    const int c = tid * 4;
    float4 gg = *(const float4*)(g + c);
    float4 bv = *(const float4*)(bb + c);
    float4 o;
    o.x = gg.x * d0 * scale + bv.x;
    o.y = gg.y * d1 * scale + bv.y;
    o.z = gg.z * d2 * scale + bv.z;
    o.w = gg.w * d3 * scale + bv.w;
    *(float4*)(out + base) = o;
}

__global__ void kd_dot(const float* __restrict__ H, const float* __restrict__ w,
                       const float* __restrict__ bias, float* __restrict__ out)
{
    __shared__ float red[256];
    const int row = blockIdx.x, tid = threadIdx.x;
    float4 h = *(const float4*)(H + (size_t)row * DIM + tid * 4);
    float4 ww = *(const float4*)(w + tid * 4);
    red[tid] = h.x * ww.x + h.y * ww.y + h.z * ww.z + h.w * ww.w;
    __syncthreads();
    for (int s = 128; s > 0; s >>= 1) { if (tid < s) red[tid] += red[tid + s]; __syncthreads(); }
    if (tid == 0) out[row] = red[0] + bias[0];
}

// ---------------------------------------------------------------------------
extern "C" void kernel_launch(void* const* d_in, const int* in_sizes, int n_in,
                              void* d_out, int out_size)
{
    (void)in_sizes; (void)n_in; (void)out_size;

    const float* x1   = (const float*)d_in[0];
    const float* x2   = (const float*)d_in[1];
    const float* x3   = (const float*)d_in[2];
    const float* Wk   = (const float*)d_in[3];
    const float* Wq   = (const float*)d_in[4];
    const float* Wv   = (const float*)d_in[5];
    const float* Wo   = (const float*)d_in[6];
    const float* ka_w = (const float*)d_in[7];
    const float* ka_b = (const float*)d_in[8];
    const float* kb_w = (const float*)d_in[9];
    const float* kb_b = (const float*)d_in[10];
    const float* kc_w = (const float*)d_in[11];
    const float* kc_b = (const float*)d_in[12];
    const float* kd_w = (const float*)d_in[13];
    const float* kd_b = (const float*)d_in[14];
    const float* g1   = (const float*)d_in[15];
    const float* b1   = (const float*)d_in[16];
    const float* g2   = (const float*)d_in[17];
    const float* b2   = (const float*)d_in[18];
    float* out = (float*)d_out;

    float* scratch = nullptr;
    cudaGetSymbolAddress((void**)&scratch, g_scratch);

    __nv_bfloat16* Khi[2]; __nv_bfloat16* Klo[2];
    __nv_bfloat16* Qhi[2]; __nv_bfloat16* Qlo[2];
    __nv_bfloat16* Vhi[2]; __nv_bfloat16* Vlo[2];
    float* bAp[2];
    for (int p = 0; p < 2; p++) {
        float* base = scratch + (size_t)p * 3 * RD;
        Khi[p] = (__nv_bfloat16*)(base);
        Klo[p] = (__nv_bfloat16*)(base + (size_t)RD / 2);
        Qhi[p] = (__nv_bfloat16*)(base + (size_t)RD);
        Qlo[p] = (__nv_bfloat16*)(base + (size_t)RD * 3 / 2);
        Vhi[p] = (__nv_bfloat16*)(base + (size_t)RD * 2);
        Vlo[p] = (__nv_bfloat16*)(base + (size_t)RD * 5 / 2);
        bAp[p] = scratch + (size_t)RD * 6 + (size_t)p * RD;
    }
    float* ySum  = scratch + (size_t)RD * 8;
    float* woOut = scratch + (size_t)RD * 9;
    float* band  = scratch + (size_t)RD * 10;

    static cudaStream_t sA = nullptr, sB = nullptr, sC = nullptr;
    static cudaEvent_t e0, eD, eMLP, eK[3], eQ[3], eV[3], eBL[3], eBA[3], eWo[3];
    if (sA == nullptr) {
        cudaStreamCreateWithFlags(&sA, cudaStreamNonBlocking);
        cudaStreamCreateWithFlags(&sB, cudaStreamNonBlocking);
        cudaStreamCreateWithFlags(&sC, cudaStreamNonBlocking);
        cudaEventCreateWithFlags(&e0, cudaEventDisableTiming);
        cudaEventCreateWithFlags(&eD, cudaEventDisableTiming);
        cudaEventCreateWithFlags(&eMLP, cudaEventDisableTiming);
        for (int t = 0; t < 3; t++) {
            cudaEventCreateWithFlags(&eK[t], cudaEventDisableTiming);
            cudaEventCreateWithFlags(&eQ[t], cudaEventDisableTiming);
            cudaEventCreateWithFlags(&eV[t], cudaEventDisableTiming);
            cudaEventCreateWithFlags(&eBL[t], cudaEventDisableTiming);
            cudaEventCreateWithFlags(&eBA[t], cudaEventDisableTiming);
            cudaEventCreateWithFlags(&eWo[t], cudaEventDisableTiming);
        }
    }

    cudaFuncSetAttribute(tgemm, cudaFuncAttributeMaxDynamicSharedMemorySize, SMT);
    cudaFuncSetAttribute(band_logits_mma, cudaFuncAttributeMaxDynamicSharedMemorySize, BL_SMT);
    cudaFuncSetAttribute(band_apply_mma, cudaFuncAttributeMaxDynamicSharedMemorySize, BA_SMT);

    const dim3 gT(DIM / 128, RTOT / 128);
    const dim3 gH(DIM / 128, RTOT / 256);   // half-M grid for MLP pipelining
    const dim3 gL(BANDW / 128, RTOT / 64);
    const dim3 gA(DIM / 64, RTOT / 64);
    const cudaStream_t s0 = 0;
    const float* xs[3] = {x1, x2, x3};
    const int HROWS = RTOT / 2;
    const size_t HOFF = (size_t)HROWS * DIM;

    cudaMemsetAsync(ySum, 0, sizeof(float) * (size_t)RD, s0);
    cudaEventRecord(e0, s0);

    // Prelaunch K/Q/V for towers 0 and 1.
    for (int t = 0; t < 2; t++) {
        const int p = t & 1;
        cudaStreamWaitEvent(sA, e0, 0);
        tgemm<<<gT, 256, SMT, sA>>>(xs[t], Wk, nullptr, nullptr, Khi[p], Klo[p], DIM, 1.0f, 0);
        cudaEventRecord(eK[t], sA);
        cudaStreamWaitEvent(sB, e0, 0);
        tgemm<<<gT, 256, SMT, sB>>>(xs[t], Wq, nullptr, nullptr, Qhi[p], Qlo[p], DIM, 0.06f, 0);
        cudaEventRecord(eQ[t], sB);
        cudaStreamWaitEvent(sC, e0, 0);
        tgemm<<<gT, 256, SMT, sC>>>(xs[t], Wv, nullptr, nullptr, Vhi[p], Vlo[p], DIM, 1.0f, 0);
        cudaEventRecord(eV[t], sC);
    }

    for (int t = 0; t < 3; t++) {
        const float* x = xs[t];
        const int p = t & 1;

        cudaStreamWaitEvent(s0, eK[t], 0);
        cudaStreamWaitEvent(s0, eQ[t], 0);
        band_logits_mma<<<gL, 256, BL_SMT, s0>>>(Qhi[p], Qlo[p], Khi[p], Klo[p], band);
        cudaEventRecord(eBL[t], s0);

        if (t + 2 < 3) {
            const int p2 = (t + 2) & 1;
            cudaStreamWaitEvent(sA, eBL[t], 0);
            tgemm<<<gT, 256, SMT, sA>>>(xs[t + 2], Wk, nullptr, nullptr, Khi[p2], Klo[p2], DIM, 1.0f, 0);
            cudaEventRecord(eK[t + 2], sA);
            cudaStreamWaitEvent(sB, eBL[t], 0);
            tgemm<<<gT, 256, SMT, sB>>>(xs[t + 2], Wq, nullptr, nullptr, Qhi[p2], Qlo[p2], DIM, 0.06f, 0);
            cudaEventRecord(eQ[t + 2], sB);
        }

        band_softmax<<<RTOT, 256, 0, s0>>>(band);
        cudaStreamWaitEvent(s0, eV[t], 0);
        if (t >= 2) cudaStreamWaitEvent(s0, eWo[t - 2], 0);
        band_apply_mma<<<gA, 256, BA_SMT, s0>>>(band, Vhi[p], Vlo[p], bAp[p]);
        cudaEventRecord(eBA[t], s0);

        if (t + 2 < 3) {
            const int p2 = (t + 2) & 1;
            cudaStreamWaitEvent(sC, eBA[t], 0);
            tgemm<<<gT, 256, SMT, sC>>>(xs[t + 2], Wv, nullptr, nullptr, Vhi[p2], Vlo[p2], DIM, 1.0f, 0);
            cudaEventRecord(eV[t + 2], sC);
        }

        cudaStreamWaitEvent(sC, eBA[t], 0);
        tgemm<<<gT, 256, SMT, sC>>>(bAp[p], Wo, nullptr, woOut, nullptr, nullptr, DIM, 1.0f, 0);
        cudaEventRecord(eWo[t], sC);
        addln_acc<<<RTOT, 256, 0, sC>>>(woOut, x, g1, b1, ySum);
    }
    cudaEventRecord(eD, sC);

    // MLP chain, row-split into two halves pipelined on s0 / sA.
    // h0 on s0
    cudaStreamWaitEvent(s0, eD, 0);
    tgemm<<<gH, 256, SMT, s0>>>(ySum, ka_w, ka_b, bAp[0], nullptr, nullptr, DIM, 1.0f, 0);
    tgemm<<<gH, 256, SMT, s0>>>(bAp[0], kb_w, kb_b, woOut, nullptr, nullptr, DIM, 1.0f, 0);
    tgemm<<<gH, 256, SMT, s0>>>(woOut, kc_w, kc_b, bAp[0], nullptr, nullptr, DIM, 1.0f, 1);
    ln_only<<<HROWS, 256, 0, s0>>>(bAp[0], g2, b2, woOut);
    kd_dot<<<HROWS, 256, 0, s0>>>(woOut, kd_w, kd_b, out);
    // h1 on sA (fully independent rows)
    cudaStreamWaitEvent(sA, eD, 0);
    tgemm<<<gH, 256, SMT, sA>>>(ySum + HOFF, ka_w, ka_b, bAp[0] + HOFF, nullptr, nullptr, DIM, 1.0f, 0);
    tgemm<<<gH, 256, SMT, sA>>>(bAp[0] + HOFF, kb_w, kb_b, woOut + HOFF, nullptr, nullptr, DIM, 1.0f, 0);
    tgemm<<<gH, 256, SMT, sA>>>(woOut + HOFF, kc_w, kc_b, bAp[0] + HOFF, nullptr, nullptr, DIM, 1.0f, 1);
    ln_only<<<HROWS, 256, 0, sA>>>(bAp[0] + HOFF, g2, b2, woOut + HOFF);
    kd_dot<<<HROWS, 256, 0, sA>>>(woOut + HOFF, kd_w, kd_b, out + HROWS);
    cudaEventRecord(eMLP, sA);
    cudaStreamWaitEvent(s0, eMLP, 0);
}